// round 1
// baseline (speedup 1.0000x reference)
#include <cuda_runtime.h>
#include <cuda_fp16.h>
#include <cuda_bf16.h>
#include <cstdint>

// Problem constants
#define NN   8192
#define FIN  512
#define FOUT 64
#define NEXT 80     // h_ext cols: 64 features + col64 = ones + pad to 80
#define SPLITS 8
#define JPER  (NN / SPLITS)   // 1024 j per split
#define BK    64
#define CHUNKS (JPER / BK)    // 16

// -------- scratch (static device globals; no allocations allowed) --------
__device__ float  g_h[NN * FOUT];               // 2 MB   fp32 h = inp@W
__device__ float4 g_row[NN];                    // (f1, exp(f1), exp(0.2 f1), 0)
__device__ float4 g_col[NN];                    // (f2, exp(f2), exp(0.2 f2), 0)
__device__ __half g_hextT[NEXT * NN];           // 1.31 MB  transposed h_ext fp16
__device__ float  g_partial[SPLITS * NN * NEXT]; // 21 MB   per-split accumulators

// -------- packed f32x2 FMA (Blackwell) --------
#define FMA_F32X2(d, a, b, c) \
    asm("fma.rn.f32x2 %0, %1, %2, %3;" : "=l"(d) : "l"(a), "l"(b), "l"(c))

__device__ __forceinline__ void mma16816(float* c, const uint32_t* a, const uint32_t* b) {
    asm volatile(
        "mma.sync.aligned.m16n8k16.row.col.f32.f16.f16.f32 "
        "{%0,%1,%2,%3}, {%4,%5,%6,%7}, {%8,%9}, {%0,%1,%2,%3};"
        : "+f"(c[0]), "+f"(c[1]), "+f"(c[2]), "+f"(c[3])
        : "r"(a[0]), "r"(a[1]), "r"(a[2]), "r"(a[3]), "r"(b[0]), "r"(b[1]));
}

// ==================== K1: h = inp @ W  (fp32, f32x2 packed) ====================
// grid 128 blocks (64 rows each), 256 threads. Even/odd k split across f32x2 lanes.
__global__ __launch_bounds__(256) void k1_gemm(const float* __restrict__ inp,
                                               const float* __restrict__ W) {
    __shared__ float inp_s[64][68];   // [row][k]
    __shared__ float w_sT[64][68];    // [f][k]  (transposed W tile)
    const int t  = threadIdx.x;
    const int i0 = blockIdx.x * 64;
    const int tx = t & 15;            // col group (4 cols)
    const int ty = t >> 4;            // row group (4 rows)

    unsigned long long acc2[4][4];
#pragma unroll
    for (int q = 0; q < 4; q++)
#pragma unroll
        for (int c = 0; c < 4; c++) acc2[q][c] = 0ULL;

    for (int kc = 0; kc < FIN; kc += 64) {
#pragma unroll
        for (int m = 0; m < 4; m++) {
            int lin = t + 256 * m;
            int row = lin >> 4, seg = lin & 15;
            float4 v  = *(const float4*)&inp[(i0 + row) * FIN + kc + seg * 4];
            *(float4*)&inp_s[row][seg * 4] = v;
            float4 wv = *(const float4*)&W[(kc + row) * FOUT + seg * 4];
            w_sT[seg * 4 + 0][row] = wv.x;
            w_sT[seg * 4 + 1][row] = wv.y;
            w_sT[seg * 4 + 2][row] = wv.z;
            w_sT[seg * 4 + 3][row] = wv.w;
        }
        __syncthreads();
#pragma unroll 4
        for (int kk = 0; kk < 64; kk += 2) {
            unsigned long long a2[4], b2[4];
#pragma unroll
            for (int q = 0; q < 4; q++)
                a2[q] = *(const unsigned long long*)&inp_s[ty * 4 + q][kk];
#pragma unroll
            for (int c = 0; c < 4; c++)
                b2[c] = *(const unsigned long long*)&w_sT[tx * 4 + c][kk];
#pragma unroll
            for (int q = 0; q < 4; q++)
#pragma unroll
                for (int c = 0; c < 4; c++)
                    FMA_F32X2(acc2[q][c], a2[q], b2[c], acc2[q][c]);
        }
        __syncthreads();
    }
#pragma unroll
    for (int q = 0; q < 4; q++)
#pragma unroll
        for (int c = 0; c < 4; c++) {
            float lo, hi;
            asm("mov.b64 {%0,%1}, %2;" : "=f"(lo), "=f"(hi) : "l"(acc2[q][c]));
            g_h[(i0 + ty * 4 + q) * FOUT + tx * 4 + c] = lo + hi;
        }
}

// ==================== K2: per-node f1/f2, exp factors, h_extT fp16 ====================
// one warp per node row; grid 1024 x 256
__global__ __launch_bounds__(256) void k2_prep(const float* __restrict__ a_vec) {
    const int row  = blockIdx.x * 8 + (threadIdx.x >> 5);
    const int lane = threadIdx.x & 31;
    float h0 = g_h[row * FOUT + lane];
    float h1 = g_h[row * FOUT + 32 + lane];
    float s1 = h0 * a_vec[lane] + h1 * a_vec[32 + lane];
    float s2 = h0 * a_vec[64 + lane] + h1 * a_vec[96 + lane];
#pragma unroll
    for (int o = 16; o > 0; o >>= 1) {
        s1 += __shfl_xor_sync(0xffffffffu, s1, o);
        s2 += __shfl_xor_sync(0xffffffffu, s2, o);
    }
    if (lane == 0) {
        g_row[row] = make_float4(s1, expf(s1), expf(0.2f * s1), 0.f);
        g_col[row] = make_float4(s2, expf(s2), expf(0.2f * s2), 0.f);
    }
    // transposed fp16 h_ext: rows 0..63 = h, row 64 = 1.0, rows 65..79 = 0
    g_hextT[lane * NN + row]        = __float2half_rn(h0);
    g_hextT[(lane + 32) * NN + row] = __float2half_rn(h1);
    if (lane < 16)
        g_hextT[(64 + lane) * NN + row] = __float2half_rn(lane == 0 ? 1.f : 0.f);
}

// ==================== K3: fused weight-gen + fp16 MMA (attention @ h_ext) ===========
// grid (128 row-blocks, 8 j-splits), 256 threads (8 warps: 4 M-slices x 2 N-halves)
__global__ __launch_bounds__(256) void k3_main(const int* __restrict__ adj) {
    __shared__ __half w_sm[64][72];    // w tile [row][j], pad 8 -> conflict-free
    __shared__ __half hT_sm[80][72];   // h_extT tile [n][j]

    const int t  = threadIdx.x;
    const int ib = blockIdx.x * 64;
    const int j0 = blockIdx.y * JPER;

    // weight-gen mapping: 4 rows x 4 j per thread
    const int r0 = (t >> 4) * 4;
    const int jc = (t & 15) * 4;
    float f1[4], Ae[4], Be[4];
#pragma unroll
    for (int rr = 0; rr < 4; rr++) {
        float4 v = g_row[ib + r0 + rr];
        f1[rr] = v.x; Ae[rr] = v.y; Be[rr] = v.z;
    }

    // mma mapping
    const int warp = t >> 5, lane = t & 31;
    const int g = lane >> 2, tq = lane & 3;
    const int mrow = (warp & 3) * 16;
    const int ncol = (warp >> 2) * 40;
    float acc[5][4];
#pragma unroll
    for (int nf = 0; nf < 5; nf++)
#pragma unroll
        for (int q = 0; q < 4; q++) acc[nf][q] = 0.f;

    for (int ch = 0; ch < CHUNKS; ch++) {
        const int jg = j0 + ch * BK;
        // --- generate w tile ---
        float4 fp[4];
#pragma unroll
        for (int jj = 0; jj < 4; jj++) fp[jj] = g_col[jg + jc + jj];
#pragma unroll
        for (int rr = 0; rr < 4; rr++) {
            const int4 av = *(const int4*)&adj[(ib + r0 + rr) * NN + jg + jc];
            float w[4];
            int am[4] = {av.x, av.y, av.z, av.w};
#pragma unroll
            for (int jj = 0; jj < 4; jj++) {
                float x  = f1[rr] + fp[jj].x;
                float wv = (x > 0.f) ? (Ae[rr] * fp[jj].y) : (Be[rr] * fp[jj].z);
                w[jj] = (am[jj] != 0) ? wv : 0.f;
            }
            __half2* dst = (__half2*)&w_sm[r0 + rr][jc];
            dst[0] = __floats2half2_rn(w[0], w[1]);
            dst[1] = __floats2half2_rn(w[2], w[3]);
        }
        // --- stage h_extT tile (80 rows x 64 halves) ---
        for (int m = t; m < 640; m += 256) {
            int n = m >> 3, seg = m & 7;
            *(uint4*)&hT_sm[n][seg * 8] = *(const uint4*)&g_hextT[n * NN + jg + seg * 8];
        }
        __syncthreads();
        // --- MMA: acc += w_tile[16x64] @ hT_tile^T[64x40] per warp ---
#pragma unroll
        for (int k16 = 0; k16 < BK; k16 += 16) {
            uint32_t a[4];
            a[0] = *(const uint32_t*)&w_sm[mrow + g][k16 + tq * 2];
            a[1] = *(const uint32_t*)&w_sm[mrow + g + 8][k16 + tq * 2];
            a[2] = *(const uint32_t*)&w_sm[mrow + g][k16 + tq * 2 + 8];
            a[3] = *(const uint32_t*)&w_sm[mrow + g + 8][k16 + tq * 2 + 8];
#pragma unroll
            for (int nf = 0; nf < 5; nf++) {
                uint32_t b[2];
                b[0] = *(const uint32_t*)&hT_sm[ncol + nf * 8 + g][k16 + tq * 2];
                b[1] = *(const uint32_t*)&hT_sm[ncol + nf * 8 + g][k16 + tq * 2 + 8];
                mma16816(acc[nf], a, b);
            }
        }
        __syncthreads();
    }
    // --- store partial accumulators ---
    float* P = &g_partial[blockIdx.y * (NN * NEXT)];
#pragma unroll
    for (int nf = 0; nf < 5; nf++) {
        int col  = ncol + nf * 8 + tq * 2;
        int row1 = ib + mrow + g;
        *(float2*)&P[row1 * NEXT + col]       = make_float2(acc[nf][0], acc[nf][1]);
        *(float2*)&P[(row1 + 8) * NEXT + col] = make_float2(acc[nf][2], acc[nf][3]);
    }
}

// ==================== K4: reduce splits, softmax divide, ELU ====================
__global__ __launch_bounds__(256) void k4_finish(float* __restrict__ out) {
    const int gid = blockIdx.x * 256 + threadIdx.x;   // 524288 total
    const int i = gid >> 6, f = gid & 63;
    float num = 0.f, den = 0.f;
#pragma unroll
    for (int s = 0; s < SPLITS; s++) {
        const float* P = &g_partial[(s * NN + i) * NEXT];
        num += P[f];
        den += P[64];
    }
    float v = num / den;
    out[gid] = (v > 0.f) ? v : expm1f(v);
}

// ==================== launcher ====================
extern "C" void kernel_launch(void* const* d_in, const int* in_sizes, int n_in,
                              void* d_out, int out_size) {
    const float* inp   = (const float*)d_in[0];   // [8192,512]
    const int*   adj   = (const int*)d_in[1];     // [8192,8192]
    const float* W     = (const float*)d_in[2];   // [512,64]
    const float* a_vec = (const float*)d_in[3];   // [128,1]
    float* out = (float*)d_out;

    k1_gemm<<<NN / 64, 256>>>(inp, W);
    k2_prep<<<NN / 8, 256>>>(a_vec);
    k3_main<<<dim3(NN / 64, SPLITS), 256>>>(adj);
    k4_finish<<<(NN * FOUT) / 256, 256>>>(out);
}

// round 2
// speedup vs baseline: 1.2910x; 1.2910x over previous
#include <cuda_runtime.h>
#include <cuda_fp16.h>
#include <cuda_bf16.h>
#include <cstdint>

// Problem constants
#define NN   8192
#define FIN  512
#define FOUT 64
#define NEXT 80     // h_ext cols: 64 features + col64 = ones + pad to 80
#define SPLITS 8
#define JPER  (NN / SPLITS)   // 1024 j per split
#define BK    64
#define CHUNKS (JPER / BK)    // 16
#define BM    128             // rows per k3 block

// -------- scratch (static device globals; no allocations allowed) --------
__device__ float  g_h[NN * FOUT];                // 2 MB   fp32 h = inp@W
__device__ float4 g_row[NN];                     // (f1, exp(f1), exp(0.2 f1), 0)
__device__ float4 g_col[NN];                     // (f2, exp(f2), exp(0.2 f2), 0)
__device__ __half g_hextT[NEXT * NN];            // 1.31 MB transposed h_ext fp16
__device__ float  g_partial[SPLITS * NN * NEXT]; // 21 MB  per-split accumulators

// -------- packed f32x2 FMA (Blackwell) --------
#define FMA_F32X2(d, a, b, c) \
    asm("fma.rn.f32x2 %0, %1, %2, %3;" : "=l"(d) : "l"(a), "l"(b), "l"(c))

__device__ __forceinline__ void mma16816(float* c, const uint32_t* a, const uint32_t* b) {
    asm volatile(
        "mma.sync.aligned.m16n8k16.row.col.f32.f16.f16.f32 "
        "{%0,%1,%2,%3}, {%4,%5,%6,%7}, {%8,%9}, {%0,%1,%2,%3};"
        : "+f"(c[0]), "+f"(c[1]), "+f"(c[2]), "+f"(c[3])
        : "r"(a[0]), "r"(a[1]), "r"(a[2]), "r"(a[3]), "r"(b[0]), "r"(b[1]));
}

__device__ __forceinline__ float wgen(const float4 r, const float4 c, int m) {
    float x = r.x + c.x;
    float w = (x > 0.f) ? r.y * c.y : r.z * c.z;
    return m ? w : 0.f;
}

__device__ __forceinline__ uint32_t packh2(float lo, float hi) {
    __half2 h = __floats2half2_rn(lo, hi);
    return *(uint32_t*)&h;
}

// ==================== K1: h = inp @ W  (fp32, f32x2 packed) ====================
__global__ __launch_bounds__(256) void k1_gemm(const float* __restrict__ inp,
                                               const float* __restrict__ W) {
    __shared__ float inp_s[64][68];   // [row][k]
    __shared__ float w_sT[64][68];    // [f][k]  (transposed W tile)
    const int t  = threadIdx.x;
    const int i0 = blockIdx.x * 64;
    const int tx = t & 15;            // col group (4 cols)
    const int ty = t >> 4;            // row group (4 rows)

    unsigned long long acc2[4][4];
#pragma unroll
    for (int q = 0; q < 4; q++)
#pragma unroll
        for (int c = 0; c < 4; c++) acc2[q][c] = 0ULL;

    for (int kc = 0; kc < FIN; kc += 64) {
#pragma unroll
        for (int m = 0; m < 4; m++) {
            int lin = t + 256 * m;
            int row = lin >> 4, seg = lin & 15;
            float4 v  = *(const float4*)&inp[(i0 + row) * FIN + kc + seg * 4];
            *(float4*)&inp_s[row][seg * 4] = v;
            float4 wv = *(const float4*)&W[(kc + row) * FOUT + seg * 4];
            w_sT[seg * 4 + 0][row] = wv.x;
            w_sT[seg * 4 + 1][row] = wv.y;
            w_sT[seg * 4 + 2][row] = wv.z;
            w_sT[seg * 4 + 3][row] = wv.w;
        }
        __syncthreads();
#pragma unroll 4
        for (int kk = 0; kk < 64; kk += 2) {
            unsigned long long a2[4], b2[4];
#pragma unroll
            for (int q = 0; q < 4; q++)
                a2[q] = *(const unsigned long long*)&inp_s[ty * 4 + q][kk];
#pragma unroll
            for (int c = 0; c < 4; c++)
                b2[c] = *(const unsigned long long*)&w_sT[tx * 4 + c][kk];
#pragma unroll
            for (int q = 0; q < 4; q++)
#pragma unroll
                for (int c = 0; c < 4; c++)
                    FMA_F32X2(acc2[q][c], a2[q], b2[c], acc2[q][c]);
        }
        __syncthreads();
    }
#pragma unroll
    for (int q = 0; q < 4; q++)
#pragma unroll
        for (int c = 0; c < 4; c++) {
            float lo, hi;
            asm("mov.b64 {%0,%1}, %2;" : "=f"(lo), "=f"(hi) : "l"(acc2[q][c]));
            g_h[(i0 + ty * 4 + q) * FOUT + tx * 4 + c] = lo + hi;
        }
}

// ==================== K2: per-node f1/f2, exp factors, h_extT fp16 ==============
__global__ __launch_bounds__(256) void k2_prep(const float* __restrict__ a_vec) {
    const int row  = blockIdx.x * 8 + (threadIdx.x >> 5);
    const int lane = threadIdx.x & 31;
    float h0 = g_h[row * FOUT + lane];
    float h1 = g_h[row * FOUT + 32 + lane];
    float s1 = h0 * a_vec[lane] + h1 * a_vec[32 + lane];
    float s2 = h0 * a_vec[64 + lane] + h1 * a_vec[96 + lane];
#pragma unroll
    for (int o = 16; o > 0; o >>= 1) {
        s1 += __shfl_xor_sync(0xffffffffu, s1, o);
        s2 += __shfl_xor_sync(0xffffffffu, s2, o);
    }
    if (lane == 0) {
        g_row[row] = make_float4(s1, expf(s1), expf(0.2f * s1), 0.f);
        g_col[row] = make_float4(s2, expf(s2), expf(0.2f * s2), 0.f);
    }
    g_hextT[lane * NN + row]        = __float2half_rn(h0);
    g_hextT[(lane + 32) * NN + row] = __float2half_rn(h1);
    if (lane < 16)
        g_hextT[(64 + lane) * NN + row] = __float2half_rn(lane == 0 ? 1.f : 0.f);
}

// ==================== K3: fused weight-gen (in-register A-frags) + fp16 MMA ======
// grid (64 row-blocks, 8 j-splits), 256 threads = 8 warps, each warp: 16 rows x 80 N.
__global__ __launch_bounds__(256) void k3_main(const int* __restrict__ adj) {
    __shared__ __half  hT_sm[2][80][72];   // [buf][n][j-in-chunk], pad 72 -> no conflicts
    __shared__ float4  col_sm[2][64];      // [buf][j-in-chunk] = g_col factors

    const int t    = threadIdx.x;
    const int warp = t >> 5, lane = t & 31;
    const int g    = lane >> 2, tq = lane & 3;
    const int ib   = blockIdx.x * BM;
    const int j0   = blockIdx.y * JPER;

    const int ra = ib + warp * 16 + g;
    const int rb = ra + 8;
    const float4 va = g_row[ra];
    const float4 vb = g_row[rb];

    const int* adjA = adj + (size_t)ra * NN + j0 + tq * 2;
    const int* adjB = adj + (size_t)rb * NN + j0 + tq * 2;

    float acc[10][4];
#pragma unroll
    for (int nf = 0; nf < 10; nf++)
#pragma unroll
        for (int q = 0; q < 4; q++) acc[nf][q] = 0.f;

    auto stage = [&](int buf, int ch) {
        const int jg = j0 + ch * BK;
        for (int m = t; m < 640; m += 256) {
            int n = m >> 3, seg = m & 7;
            *(uint4*)&hT_sm[buf][n][seg * 8] =
                *(const uint4*)&g_hextT[n * NN + jg + seg * 8];
        }
        if (t < 64) col_sm[buf][t] = g_col[jg + t];
    };

    stage(0, 0);

    for (int ch = 0; ch < CHUNKS; ch++) {
        const int buf = ch & 1;

        // issue all adj loads for this chunk BEFORE the barrier (no smem dep)
        int2 A0[4], A1[4], B0[4], B1[4];
#pragma unroll
        for (int k16 = 0; k16 < 4; k16++) {
            const int off = ch * BK + k16 * 16;
            A0[k16] = *(const int2*)&adjA[off];
            A1[k16] = *(const int2*)&adjA[off + 8];
            B0[k16] = *(const int2*)&adjB[off];
            B1[k16] = *(const int2*)&adjB[off + 8];
        }

        __syncthreads();                       // hT/col for chunk ch ready
        if (ch + 1 < CHUNKS) stage(buf ^ 1, ch + 1);

#pragma unroll
        for (int k16 = 0; k16 < 4; k16++) {
            const int kb = k16 * 16 + tq * 2;
            const float4 c0 = col_sm[buf][kb];
            const float4 c1 = col_sm[buf][kb + 1];
            const float4 c8 = col_sm[buf][kb + 8];
            const float4 c9 = col_sm[buf][kb + 9];

            uint32_t a[4];
            a[0] = packh2(wgen(va, c0, A0[k16].x), wgen(va, c1, A0[k16].y));
            a[1] = packh2(wgen(vb, c0, B0[k16].x), wgen(vb, c1, B0[k16].y));
            a[2] = packh2(wgen(va, c8, A1[k16].x), wgen(va, c9, A1[k16].y));
            a[3] = packh2(wgen(vb, c8, B1[k16].x), wgen(vb, c9, B1[k16].y));

#pragma unroll
            for (int nf = 0; nf < 10; nf++) {
                uint32_t b[2];
                b[0] = *(const uint32_t*)&hT_sm[buf][nf * 8 + g][kb];
                b[1] = *(const uint32_t*)&hT_sm[buf][nf * 8 + g][kb + 8];
                mma16816(acc[nf], a, b);
            }
        }
    }

    float* P = &g_partial[blockIdx.y * (NN * NEXT)];
#pragma unroll
    for (int nf = 0; nf < 10; nf++) {
        const int col = nf * 8 + tq * 2;
        *(float2*)&P[ra * NEXT + col] = make_float2(acc[nf][0], acc[nf][1]);
        *(float2*)&P[rb * NEXT + col] = make_float2(acc[nf][2], acc[nf][3]);
    }
}

// ==================== K4: reduce splits, softmax divide, ELU ====================
__global__ __launch_bounds__(256) void k4_finish(float* __restrict__ out) {
    const int gid = blockIdx.x * 256 + threadIdx.x;   // 524288 total
    const int i = gid >> 6, f = gid & 63;
    float num = 0.f, den = 0.f;
#pragma unroll
    for (int s = 0; s < SPLITS; s++) {
        const float* P = &g_partial[(s * NN + i) * NEXT];
        num += P[f];
        den += P[64];
    }
    float v = num / den;
    out[gid] = (v > 0.f) ? v : expm1f(v);
}

// ==================== launcher ====================
extern "C" void kernel_launch(void* const* d_in, const int* in_sizes, int n_in,
                              void* d_out, int out_size) {
    const float* inp   = (const float*)d_in[0];   // [8192,512]
    const int*   adj   = (const int*)d_in[1];     // [8192,8192]
    const float* W     = (const float*)d_in[2];   // [512,64]
    const float* a_vec = (const float*)d_in[3];   // [128,1]
    float* out = (float*)d_out;

    k1_gemm<<<NN / 64, 256>>>(inp, W);
    k2_prep<<<NN / 8, 256>>>(a_vec);
    k3_main<<<dim3(NN / BM, SPLITS), 256>>>(adj);
    k4_finish<<<(NN * FOUT) / 256, 256>>>(out);
}

// round 3
// speedup vs baseline: 1.3319x; 1.0317x over previous
#include <cuda_runtime.h>
#include <cuda_fp16.h>
#include <cuda_bf16.h>
#include <cstdint>

// Problem constants
#define NN   8192
#define FIN  512
#define FOUT 64
#define NEXT 72     // h_ext cols: 64 features + col64 = ones + 7 pad (n8 granularity)
#define NF   9      // NEXT / 8 mma n-tiles
#define SPLITS 8
#define JPER  (NN / SPLITS)   // 1024 j per split
#define BK    64
#define CHUNKS (JPER / BK)    // 16
#define BM    128             // rows per k3 block

// -------- scratch (static device globals; no allocations allowed) --------
__device__ float  g_h[NN * FOUT];                // 2 MB   fp32 h = inp@W
__device__ float4 g_row[NN];                     // (f1, exp(f1), exp(0.2 f1), 0)
__device__ float4 g_col[NN];                     // (f2, exp(f2), exp(0.2 f2), 0)
__device__ __half g_hextT[NEXT * NN];            // 1.18 MB transposed h_ext fp16
__device__ float  g_partial[SPLITS * NN * NEXT]; // 18.9 MB per-split accumulators

// -------- packed f32x2 FMA (Blackwell) --------
#define FMA_F32X2(d, a, b, c) \
    asm("fma.rn.f32x2 %0, %1, %2, %3;" : "=l"(d) : "l"(a), "l"(b), "l"(c))

__device__ __forceinline__ void mma16816(float* c, const uint32_t* a, const uint32_t* b) {
    asm volatile(
        "mma.sync.aligned.m16n8k16.row.col.f32.f16.f16.f32 "
        "{%0,%1,%2,%3}, {%4,%5,%6,%7}, {%8,%9}, {%0,%1,%2,%3};"
        : "+f"(c[0]), "+f"(c[1]), "+f"(c[2]), "+f"(c[3])
        : "r"(a[0]), "r"(a[1]), "r"(a[2]), "r"(a[3]), "r"(b[0]), "r"(b[1]));
}

__device__ __forceinline__ float wgen(float rx, float ry, float rz,
                                      const float4 c, int m) {
    float x = rx + c.x;
    float w = (x > 0.f) ? ry * c.y : rz * c.z;
    return m ? w : 0.f;
}

__device__ __forceinline__ uint32_t packh2(float lo, float hi) {
    __half2 h = __floats2half2_rn(lo, hi);
    return *(uint32_t*)&h;
}

// ==================== K1: h = inp @ W  (fp32, f32x2 packed) ====================
__global__ __launch_bounds__(256) void k1_gemm(const float* __restrict__ inp,
                                               const float* __restrict__ W) {
    __shared__ float inp_s[64][68];   // [row][k]
    __shared__ float w_sT[64][68];    // [f][k]  (transposed W tile)
    const int t  = threadIdx.x;
    const int i0 = blockIdx.x * 64;
    const int tx = t & 15;            // col group (4 cols)
    const int ty = t >> 4;            // row group (4 rows)

    unsigned long long acc2[4][4];
#pragma unroll
    for (int q = 0; q < 4; q++)
#pragma unroll
        for (int c = 0; c < 4; c++) acc2[q][c] = 0ULL;

    for (int kc = 0; kc < FIN; kc += 64) {
#pragma unroll
        for (int m = 0; m < 4; m++) {
            int lin = t + 256 * m;
            int row = lin >> 4, seg = lin & 15;
            float4 v  = *(const float4*)&inp[(i0 + row) * FIN + kc + seg * 4];
            *(float4*)&inp_s[row][seg * 4] = v;
            float4 wv = *(const float4*)&W[(kc + row) * FOUT + seg * 4];
            w_sT[seg * 4 + 0][row] = wv.x;
            w_sT[seg * 4 + 1][row] = wv.y;
            w_sT[seg * 4 + 2][row] = wv.z;
            w_sT[seg * 4 + 3][row] = wv.w;
        }
        __syncthreads();
#pragma unroll 4
        for (int kk = 0; kk < 64; kk += 2) {
            unsigned long long a2[4], b2[4];
#pragma unroll
            for (int q = 0; q < 4; q++)
                a2[q] = *(const unsigned long long*)&inp_s[ty * 4 + q][kk];
#pragma unroll
            for (int c = 0; c < 4; c++)
                b2[c] = *(const unsigned long long*)&w_sT[tx * 4 + c][kk];
#pragma unroll
            for (int q = 0; q < 4; q++)
#pragma unroll
                for (int c = 0; c < 4; c++)
                    FMA_F32X2(acc2[q][c], a2[q], b2[c], acc2[q][c]);
        }
        __syncthreads();
    }
#pragma unroll
    for (int q = 0; q < 4; q++)
#pragma unroll
        for (int c = 0; c < 4; c++) {
            float lo, hi;
            asm("mov.b64 {%0,%1}, %2;" : "=f"(lo), "=f"(hi) : "l"(acc2[q][c]));
            g_h[(i0 + ty * 4 + q) * FOUT + tx * 4 + c] = lo + hi;
        }
}

// ==================== K2: per-node f1/f2, exp factors, h_extT fp16 ==============
__global__ __launch_bounds__(256) void k2_prep(const float* __restrict__ a_vec) {
    const int row  = blockIdx.x * 8 + (threadIdx.x >> 5);
    const int lane = threadIdx.x & 31;
    float h0 = g_h[row * FOUT + lane];
    float h1 = g_h[row * FOUT + 32 + lane];
    float s1 = h0 * a_vec[lane] + h1 * a_vec[32 + lane];
    float s2 = h0 * a_vec[64 + lane] + h1 * a_vec[96 + lane];
#pragma unroll
    for (int o = 16; o > 0; o >>= 1) {
        s1 += __shfl_xor_sync(0xffffffffu, s1, o);
        s2 += __shfl_xor_sync(0xffffffffu, s2, o);
    }
    if (lane == 0) {
        g_row[row] = make_float4(s1, expf(s1), expf(0.2f * s1), 0.f);
        g_col[row] = make_float4(s2, expf(s2), expf(0.2f * s2), 0.f);
    }
    g_hextT[lane * NN + row]        = __float2half_rn(h0);
    g_hextT[(lane + 32) * NN + row] = __float2half_rn(h1);
    if (lane < 8)
        g_hextT[(64 + lane) * NN + row] = __float2half_rn(lane == 0 ? 1.f : 0.f);
}

// ==================== K3: fused weight-gen (in-register A-frags) + fp16 MMA ======
// grid (64 row-blocks, 8 j-splits), 256 threads = 8 warps, each warp: 16 rows x 72 N.
// __launch_bounds__(256, 2): cap regs at 128 -> 2 blocks/SM -> 4 warps/SMSP.
__global__ __launch_bounds__(256, 2) void k3_main(const int* __restrict__ adj) {
    __shared__ __half  hT_sm[2][NEXT][72];  // [buf][n][j-in-chunk], pad 72
    __shared__ float4  col_sm[2][64];       // [buf][j-in-chunk] = g_col factors

    const int t    = threadIdx.x;
    const int warp = t >> 5, lane = t & 31;
    const int g    = lane >> 2, tq = lane & 3;
    const int ib   = blockIdx.x * BM;
    const int j0   = blockIdx.y * JPER;

    const int ra = ib + warp * 16 + g;
    const int rb = ra + 8;
    const float4 va4 = g_row[ra];
    const float4 vb4 = g_row[rb];
    const float vax = va4.x, vay = va4.y, vaz = va4.z;
    const float vbx = vb4.x, vby = vb4.y, vbz = vb4.z;

    const int* adjA = adj + (size_t)ra * NN + j0 + tq * 2;
    const int* adjB = adj + (size_t)rb * NN + j0 + tq * 2;

    float acc[NF][4];
#pragma unroll
    for (int nf = 0; nf < NF; nf++)
#pragma unroll
        for (int q = 0; q < 4; q++) acc[nf][q] = 0.f;

    auto stage = [&](int buf, int ch) {
        const int jg = j0 + ch * BK;
        for (int m = t; m < NEXT * 8; m += 256) {
            int n = m >> 3, seg = m & 7;
            *(uint4*)&hT_sm[buf][n][seg * 8] =
                *(const uint4*)&g_hextT[n * NN + jg + seg * 8];
        }
        if (t < 64) col_sm[buf][t] = g_col[jg + t];
    };

    stage(0, 0);

    for (int ch = 0; ch < CHUNKS; ch++) {
        const int buf = ch & 1;

        // issue all adj loads for this chunk BEFORE the barrier (no smem dep)
        int2 A0[4], A1[4], B0[4], B1[4];
#pragma unroll
        for (int k16 = 0; k16 < 4; k16++) {
            const int off = ch * BK + k16 * 16;
            A0[k16] = *(const int2*)&adjA[off];
            A1[k16] = *(const int2*)&adjA[off + 8];
            B0[k16] = *(const int2*)&adjB[off];
            B1[k16] = *(const int2*)&adjB[off + 8];
        }

        __syncthreads();                       // hT/col for chunk ch ready
        if (ch + 1 < CHUNKS) stage(buf ^ 1, ch + 1);

#pragma unroll
        for (int k16 = 0; k16 < 4; k16++) {
            const int kb = k16 * 16 + tq * 2;
            const float4 c0 = col_sm[buf][kb];
            const float4 c1 = col_sm[buf][kb + 1];
            const float4 c8 = col_sm[buf][kb + 8];
            const float4 c9 = col_sm[buf][kb + 9];

            uint32_t a[4];
            a[0] = packh2(wgen(vax, vay, vaz, c0, A0[k16].x),
                          wgen(vax, vay, vaz, c1, A0[k16].y));
            a[1] = packh2(wgen(vbx, vby, vbz, c0, B0[k16].x),
                          wgen(vbx, vby, vbz, c1, B0[k16].y));
            a[2] = packh2(wgen(vax, vay, vaz, c8, A1[k16].x),
                          wgen(vax, vay, vaz, c9, A1[k16].y));
            a[3] = packh2(wgen(vbx, vby, vbz, c8, B1[k16].x),
                          wgen(vbx, vby, vbz, c9, B1[k16].y));

#pragma unroll
            for (int nf = 0; nf < NF; nf++) {
                uint32_t b[2];
                b[0] = *(const uint32_t*)&hT_sm[buf][nf * 8 + g][kb];
                b[1] = *(const uint32_t*)&hT_sm[buf][nf * 8 + g][kb + 8];
                mma16816(acc[nf], a, b);
            }
        }
    }

    float* P = &g_partial[blockIdx.y * (NN * NEXT)];
#pragma unroll
    for (int nf = 0; nf < NF; nf++) {
        const int col = nf * 8 + tq * 2;
        *(float2*)&P[ra * NEXT + col] = make_float2(acc[nf][0], acc[nf][1]);
        *(float2*)&P[rb * NEXT + col] = make_float2(acc[nf][2], acc[nf][3]);
    }
}

// ==================== K4: reduce splits, softmax divide, ELU ====================
__global__ __launch_bounds__(256) void k4_finish(float* __restrict__ out) {
    const int gid = blockIdx.x * 256 + threadIdx.x;   // 524288 total
    const int i = gid >> 6, f = gid & 63;
    float num = 0.f, den = 0.f;
#pragma unroll
    for (int s = 0; s < SPLITS; s++) {
        const float* P = &g_partial[(s * NN + i) * NEXT];
        num += P[f];
        den += P[64];
    }
    float v = num / den;
    out[gid] = (v > 0.f) ? v : expm1f(v);
}

// ==================== launcher ====================
extern "C" void kernel_launch(void* const* d_in, const int* in_sizes, int n_in,
                              void* d_out, int out_size) {
    const float* inp   = (const float*)d_in[0];   // [8192,512]
    const int*   adj   = (const int*)d_in[1];     // [8192,8192]
    const float* W     = (const float*)d_in[2];   // [512,64]
    const float* a_vec = (const float*)d_in[3];   // [128,1]
    float* out = (float*)d_out;

    k1_gemm<<<NN / 64, 256>>>(inp, W);
    k2_prep<<<NN / 8, 256>>>(a_vec);
    k3_main<<<dim3(NN / BM, SPLITS), 256>>>(adj);
    k4_finish<<<(NN * FOUT) / 256, 256>>>(out);
}

// round 5
// speedup vs baseline: 1.4134x; 1.0612x over previous
#include <cuda_runtime.h>
#include <cuda_fp16.h>
#include <cuda_bf16.h>
#include <cstdint>

// Problem constants
#define NN   8192
#define FIN  512
#define FOUT 64
#define NF   8                // 64 N cols / 8 per mma
#define SPLITS 4
#define JPER  (NN / SPLITS)   // 2048 j per split
#define BK    64
#define CHUNKS (JPER / BK)    // 32
#define BM    128             // rows per k3 block
#define HTPAD 72              // hT smem row stride (halves)

// -------- scratch (static device globals; no allocations allowed) --------
__device__ float  g_h[NN * FOUT];                // 2 MB   fp32 h = inp@W
__device__ float4 g_row[NN];                     // (f1, exp(f1), exp(0.2 f1), 0)
__device__ float4 g_col[NN];                     // (f2, exp(f2), exp(0.2 f2), 0)
__device__ __half g_hextT[FOUT * NN];            // 1 MB  transposed h fp16
__device__ float  g_partial[SPLITS * NN * FOUT]; // 8.4 MB per-split numerators
__device__ float  g_den[SPLITS * NN];            // per-split denominators

// -------- packed f32x2 FMA (Blackwell) --------
#define FMA_F32X2(d, a, b, c) \
    asm("fma.rn.f32x2 %0, %1, %2, %3;" : "=l"(d) : "l"(a), "l"(b), "l"(c))

__device__ __forceinline__ void mma16816(float* c, const uint32_t* a, const uint32_t* b) {
    asm volatile(
        "mma.sync.aligned.m16n8k16.row.col.f32.f16.f16.f32 "
        "{%0,%1,%2,%3}, {%4,%5,%6,%7}, {%8,%9}, {%0,%1,%2,%3};"
        : "+f"(c[0]), "+f"(c[1]), "+f"(c[2]), "+f"(c[3])
        : "r"(a[0]), "r"(a[1]), "r"(a[2]), "r"(a[3]), "r"(b[0]), "r"(b[1]));
}

__device__ __forceinline__ void ldsm_x4(uint32_t& r0, uint32_t& r1, uint32_t& r2,
                                        uint32_t& r3, uint32_t addr) {
    asm volatile("ldmatrix.sync.aligned.m8n8.x4.shared.b16 {%0,%1,%2,%3}, [%4];"
                 : "=r"(r0), "=r"(r1), "=r"(r2), "=r"(r3) : "r"(addr));
}

__device__ __forceinline__ uint32_t smem_u32(const void* p) {
    uint32_t a;
    asm("{ .reg .u64 t; cvta.to.shared.u64 t, %1; cvt.u32.u64 %0, t; }"
        : "=r"(a) : "l"(p));
    return a;
}

__device__ __forceinline__ float wgen(float rx, float ry, float rz,
                                      const float4 c, int m) {
    float x = rx + c.x;
    float w = (x > 0.f) ? ry * c.y : rz * c.z;
    return m ? w : 0.f;
}

__device__ __forceinline__ uint32_t packh2(float lo, float hi) {
    __half2 h = __floats2half2_rn(lo, hi);
    return *(uint32_t*)&h;
}

// ==================== K1: h = inp @ W  (fp32, f32x2 packed) ====================
__global__ __launch_bounds__(256) void k1_gemm(const float* __restrict__ inp,
                                               const float* __restrict__ W) {
    __shared__ float inp_s[64][68];
    __shared__ float w_sT[64][68];
    const int t  = threadIdx.x;
    const int i0 = blockIdx.x * 64;
    const int tx = t & 15;
    const int ty = t >> 4;

    unsigned long long acc2[4][4];
#pragma unroll
    for (int q = 0; q < 4; q++)
#pragma unroll
        for (int c = 0; c < 4; c++) acc2[q][c] = 0ULL;

    for (int kc = 0; kc < FIN; kc += 64) {
#pragma unroll
        for (int m = 0; m < 4; m++) {
            int lin = t + 256 * m;
            int row = lin >> 4, seg = lin & 15;
            float4 v  = *(const float4*)&inp[(i0 + row) * FIN + kc + seg * 4];
            *(float4*)&inp_s[row][seg * 4] = v;
            float4 wv = *(const float4*)&W[(kc + row) * FOUT + seg * 4];
            w_sT[seg * 4 + 0][row] = wv.x;
            w_sT[seg * 4 + 1][row] = wv.y;
            w_sT[seg * 4 + 2][row] = wv.z;
            w_sT[seg * 4 + 3][row] = wv.w;
        }
        __syncthreads();
#pragma unroll 4
        for (int kk = 0; kk < 64; kk += 2) {
            unsigned long long a2[4], b2[4];
#pragma unroll
            for (int q = 0; q < 4; q++)
                a2[q] = *(const unsigned long long*)&inp_s[ty * 4 + q][kk];
#pragma unroll
            for (int c = 0; c < 4; c++)
                b2[c] = *(const unsigned long long*)&w_sT[tx * 4 + c][kk];
#pragma unroll
            for (int q = 0; q < 4; q++)
#pragma unroll
                for (int c = 0; c < 4; c++)
                    FMA_F32X2(acc2[q][c], a2[q], b2[c], acc2[q][c]);
        }
        __syncthreads();
    }
#pragma unroll
    for (int q = 0; q < 4; q++)
#pragma unroll
        for (int c = 0; c < 4; c++) {
            float lo, hi;
            asm("mov.b64 {%0,%1}, %2;" : "=f"(lo), "=f"(hi) : "l"(acc2[q][c]));
            g_h[(i0 + ty * 4 + q) * FOUT + tx * 4 + c] = lo + hi;
        }
}

// ==================== K2: per-node f1/f2, exp factors, hT fp16 ==================
__global__ __launch_bounds__(256) void k2_prep(const float* __restrict__ a_vec) {
    const int row  = blockIdx.x * 8 + (threadIdx.x >> 5);
    const int lane = threadIdx.x & 31;
    float h0 = g_h[row * FOUT + lane];
    float h1 = g_h[row * FOUT + 32 + lane];
    float s1 = h0 * a_vec[lane] + h1 * a_vec[32 + lane];
    float s2 = h0 * a_vec[64 + lane] + h1 * a_vec[96 + lane];
#pragma unroll
    for (int o = 16; o > 0; o >>= 1) {
        s1 += __shfl_xor_sync(0xffffffffu, s1, o);
        s2 += __shfl_xor_sync(0xffffffffu, s2, o);
    }
    if (lane == 0) {
        g_row[row] = make_float4(s1, expf(s1), expf(0.2f * s1), 0.f);
        g_col[row] = make_float4(s2, expf(s2), expf(0.2f * s2), 0.f);
    }
    g_hextT[lane * NN + row]        = __float2half_rn(h0);
    g_hextT[(lane + 32) * NN + row] = __float2half_rn(h1);
}

// ==================== K3: fused weight-gen + fp16 MMA, SIMT denominator =========
// grid (64 row-blocks, 4 j-splits) = 256 blocks (one wave at 2 blocks/SM).
// 256 threads = 8 warps, each warp: 16 rows x 64 N.
__global__ __launch_bounds__(256, 2) void k3_main(const int* __restrict__ adj) {
    __shared__ __half  hT_sm[2][FOUT][HTPAD];  // [buf][n][j-in-chunk]
    __shared__ float4  col_sm[2][BK];          // [buf][j-in-chunk] col factors

    const int t    = threadIdx.x;
    const int warp = t >> 5, lane = t & 31;
    const int g    = lane >> 2, tq = lane & 3;
    const int ib   = blockIdx.x * BM;
    const int j0   = blockIdx.y * JPER;

    const int ra = ib + warp * 16 + g;
    const int rb = ra + 8;
    const float4 va4 = g_row[ra];
    const float4 vb4 = g_row[rb];
    const float vax = va4.x, vay = va4.y, vaz = va4.z;
    const float vbx = vb4.x, vby = vb4.y, vbz = vb4.z;

    const int* adjA = adj + (size_t)ra * NN + j0 + tq * 2;
    const int* adjB = adj + (size_t)rb * NN + j0 + tq * 2;

    // ldmatrix per-lane base offset within a buffer:
    //  row = ((lane>>4)&1)*8 + (lane&7), khalf = (lane>>3)&1
    const uint32_t hT_base = smem_u32(&hT_sm[0][0][0]);
    const uint32_t ldsm_lane_off =
        (uint32_t)((((lane >> 4) & 1) * 8 + (lane & 7)) * (HTPAD * 2) +
                   ((lane >> 3) & 1) * 16);

    float acc[NF][4];
#pragma unroll
    for (int nf = 0; nf < NF; nf++)
#pragma unroll
        for (int q = 0; q < 4; q++) acc[nf][q] = 0.f;
    float da = 0.f, db = 0.f;

    auto stage = [&](int buf, int ch) {
        const int jg = j0 + ch * BK;
        for (int m = t; m < FOUT * 8; m += 256) {
            int n = m >> 3, seg = m & 7;
            *(uint4*)&hT_sm[buf][n][seg * 8] =
                *(const uint4*)&g_hextT[n * NN + jg + seg * 8];
        }
        if (t < BK) col_sm[buf][t] = g_col[jg + t];
    };

    stage(0, 0);

    for (int ch = 0; ch < CHUNKS; ch++) {
        const int buf = ch & 1;

        // adj loads for this chunk (no smem dep) issued before the barrier
        int2 A0[4], A1[4], B0[4], B1[4];
#pragma unroll
        for (int k16 = 0; k16 < 4; k16++) {
            const int off = ch * BK + k16 * 16;
            A0[k16] = *(const int2*)&adjA[off];
            A1[k16] = *(const int2*)&adjA[off + 8];
            B0[k16] = *(const int2*)&adjB[off];
            B1[k16] = *(const int2*)&adjB[off + 8];
        }

        __syncthreads();                       // hT/col for chunk ch ready
        if (ch + 1 < CHUNKS) stage(buf ^ 1, ch + 1);

        const uint32_t hbuf = hT_base + buf * (FOUT * HTPAD * 2) + ldsm_lane_off;

#pragma unroll
        for (int k16 = 0; k16 < 4; k16++) {
            const int kb = k16 * 16 + tq * 2;
            const float4 c0 = col_sm[buf][kb];
            const float4 c1 = col_sm[buf][kb + 1];
            const float4 c8 = col_sm[buf][kb + 8];
            const float4 c9 = col_sm[buf][kb + 9];

            float wA0 = wgen(vax, vay, vaz, c0, A0[k16].x);
            float wA1 = wgen(vax, vay, vaz, c1, A0[k16].y);
            float wA8 = wgen(vax, vay, vaz, c8, A1[k16].x);
            float wA9 = wgen(vax, vay, vaz, c9, A1[k16].y);
            float wB0 = wgen(vbx, vby, vbz, c0, B0[k16].x);
            float wB1 = wgen(vbx, vby, vbz, c1, B0[k16].y);
            float wB8 = wgen(vbx, vby, vbz, c8, B1[k16].x);
            float wB9 = wgen(vbx, vby, vbz, c9, B1[k16].y);
            da += (wA0 + wA1) + (wA8 + wA9);
            db += (wB0 + wB1) + (wB8 + wB9);

            uint32_t a[4];
            a[0] = packh2(wA0, wA1);
            a[1] = packh2(wB0, wB1);
            a[2] = packh2(wA8, wA9);
            a[3] = packh2(wB8, wB9);

            const uint32_t kaddr = hbuf + (uint32_t)(k16 * 32);
#pragma unroll
            for (int nfp = 0; nfp < 4; nfp++) {
                uint32_t b00, b01, b10, b11;
                ldsm_x4(b00, b01, b10, b11,
                        kaddr + (uint32_t)(nfp * 16 * (HTPAD * 2)));
                uint32_t bl[2] = {b00, b01};
                mma16816(acc[nfp * 2], a, bl);
                uint32_t bh[2] = {b10, b11};
                mma16816(acc[nfp * 2 + 1], a, bh);
            }
        }
    }

    // denominator: reduce over the 4 tq lanes of each g-group
    da += __shfl_xor_sync(0xffffffffu, da, 1);
    da += __shfl_xor_sync(0xffffffffu, da, 2);
    db += __shfl_xor_sync(0xffffffffu, db, 1);
    db += __shfl_xor_sync(0xffffffffu, db, 2);
    if (tq == 0) {
        g_den[blockIdx.y * NN + ra] = da;
        g_den[blockIdx.y * NN + rb] = db;
    }

    float* P = &g_partial[(size_t)blockIdx.y * (NN * FOUT)];
#pragma unroll
    for (int nf = 0; nf < NF; nf++) {
        const int col = nf * 8 + tq * 2;
        *(float2*)&P[(size_t)ra * FOUT + col] = make_float2(acc[nf][0], acc[nf][1]);
        *(float2*)&P[(size_t)rb * FOUT + col] = make_float2(acc[nf][2], acc[nf][3]);
    }
}

// ==================== K4: reduce splits, softmax divide, ELU ====================
__global__ __launch_bounds__(256) void k4_finish(float* __restrict__ out) {
    const int gid = blockIdx.x * 256 + threadIdx.x;   // 524288 total
    const int i = gid >> 6, f = gid & 63;
    float num = 0.f, den = 0.f;
#pragma unroll
    for (int s = 0; s < SPLITS; s++) {
        num += g_partial[((size_t)s * NN + i) * FOUT + f];
        den += g_den[s * NN + i];
    }
    float v = num / den;
    out[gid] = (v > 0.f) ? v : expm1f(v);
}

// ==================== launcher ====================
extern "C" void kernel_launch(void* const* d_in, const int* in_sizes, int n_in,
                              void* d_out, int out_size) {
    const float* inp   = (const float*)d_in[0];   // [8192,512]
    const int*   adj   = (const int*)d_in[1];     // [8192,8192]
    const float* W     = (const float*)d_in[2];   // [512,64]
    const float* a_vec = (const float*)d_in[3];   // [128,1]
    float* out = (float*)d_out;

    k1_gemm<<<NN / 64, 256>>>(inp, W);
    k2_prep<<<NN / 8, 256>>>(a_vec);
    k3_main<<<dim3(NN / BM, SPLITS), 256>>>(adj);
    k4_finish<<<(NN * FOUT) / 256, 256>>>(out);
}

// round 6
// speedup vs baseline: 1.5494x; 1.0962x over previous
#include <cuda_runtime.h>
#include <cuda_fp16.h>
#include <cuda_bf16.h>
#include <cstdint>

// Problem constants
#define NN   8192
#define FIN  512
#define FOUT 64
#define NF   8                // 64 N cols / 8 per mma
#define SPLITS 4
#define JPER  (NN / SPLITS)   // 2048 j per split
#define BK    64
#define CHUNKS (JPER / BK)    // 32
#define BM    128             // rows per k3 block
#define PAD   72              // smem row stride in halves (144B, ldmatrix conflict-free)

// -------- scratch (static device globals; no allocations allowed) --------
__device__ float  g_h[NN * FOUT];                // 2 MB   fp32 h = inp@W
__device__ float4 g_row[NN];                     // (f1, exp(f1), exp(0.2 f1), 0)
__device__ float4 g_col[NN];                     // (f2, exp(f2), exp(0.2 f2), 0)
__device__ __half g_hextT[FOUT * NN];            // 1 MB  transposed h fp16
__device__ float  g_partial[SPLITS * NN * FOUT]; // 8.4 MB per-split numerators
__device__ float  g_den[SPLITS * NN];            // per-split denominators

// -------- packed f32x2 FMA (Blackwell) --------
#define FMA_F32X2(d, a, b, c) \
    asm("fma.rn.f32x2 %0, %1, %2, %3;" : "=l"(d) : "l"(a), "l"(b), "l"(c))

__device__ __forceinline__ void mma16816(float* c, const uint32_t* a, const uint32_t* b) {
    asm volatile(
        "mma.sync.aligned.m16n8k16.row.col.f32.f16.f16.f32 "
        "{%0,%1,%2,%3}, {%4,%5,%6,%7}, {%8,%9}, {%0,%1,%2,%3};"
        : "+f"(c[0]), "+f"(c[1]), "+f"(c[2]), "+f"(c[3])
        : "r"(a[0]), "r"(a[1]), "r"(a[2]), "r"(a[3]), "r"(b[0]), "r"(b[1]));
}

__device__ __forceinline__ void ldsm_x4(uint32_t& r0, uint32_t& r1, uint32_t& r2,
                                        uint32_t& r3, uint32_t addr) {
    asm volatile("ldmatrix.sync.aligned.m8n8.x4.shared.b16 {%0,%1,%2,%3}, [%4];"
                 : "=r"(r0), "=r"(r1), "=r"(r2), "=r"(r3) : "r"(addr));
}

__device__ __forceinline__ uint32_t smem_u32(const void* p) {
    uint32_t a;
    asm("{ .reg .u64 t; cvta.to.shared.u64 t, %1; cvt.u32.u64 %0, t; }"
        : "=r"(a) : "l"(p));
    return a;
}

__device__ __forceinline__ float wgen(float rx, float ry, float rz,
                                      const float4 c, int m) {
    float x = rx + c.x;
    float w = (x > 0.f) ? ry * c.y : rz * c.z;
    return m ? w : 0.f;
}

__device__ __forceinline__ uint32_t packh2(float lo, float hi) {
    __half2 h = __floats2half2_rn(lo, hi);
    return *(uint32_t*)&h;
}

// ==================== K1: h = inp @ W  (fp32, f32x2 packed) ====================
__global__ __launch_bounds__(256) void k1_gemm(const float* __restrict__ inp,
                                               const float* __restrict__ W) {
    __shared__ float inp_s[64][68];
    __shared__ float w_sT[64][68];
    const int t  = threadIdx.x;
    const int i0 = blockIdx.x * 64;
    const int tx = t & 15;
    const int ty = t >> 4;

    unsigned long long acc2[4][4];
#pragma unroll
    for (int q = 0; q < 4; q++)
#pragma unroll
        for (int c = 0; c < 4; c++) acc2[q][c] = 0ULL;

    for (int kc = 0; kc < FIN; kc += 64) {
#pragma unroll
        for (int m = 0; m < 4; m++) {
            int lin = t + 256 * m;
            int row = lin >> 4, seg = lin & 15;
            float4 v  = *(const float4*)&inp[(i0 + row) * FIN + kc + seg * 4];
            *(float4*)&inp_s[row][seg * 4] = v;
            float4 wv = *(const float4*)&W[(kc + row) * FOUT + seg * 4];
            w_sT[seg * 4 + 0][row] = wv.x;
            w_sT[seg * 4 + 1][row] = wv.y;
            w_sT[seg * 4 + 2][row] = wv.z;
            w_sT[seg * 4 + 3][row] = wv.w;
        }
        __syncthreads();
#pragma unroll 4
        for (int kk = 0; kk < 64; kk += 2) {
            unsigned long long a2[4], b2[4];
#pragma unroll
            for (int q = 0; q < 4; q++)
                a2[q] = *(const unsigned long long*)&inp_s[ty * 4 + q][kk];
#pragma unroll
            for (int c = 0; c < 4; c++)
                b2[c] = *(const unsigned long long*)&w_sT[tx * 4 + c][kk];
#pragma unroll
            for (int q = 0; q < 4; q++)
#pragma unroll
                for (int c = 0; c < 4; c++)
                    FMA_F32X2(acc2[q][c], a2[q], b2[c], acc2[q][c]);
        }
        __syncthreads();
    }
#pragma unroll
    for (int q = 0; q < 4; q++)
#pragma unroll
        for (int c = 0; c < 4; c++) {
            float lo, hi;
            asm("mov.b64 {%0,%1}, %2;" : "=f"(lo), "=f"(hi) : "l"(acc2[q][c]));
            g_h[(i0 + ty * 4 + q) * FOUT + tx * 4 + c] = lo + hi;
        }
}

// ==================== K2: per-node f1/f2, exp factors, hT fp16 ==================
__global__ __launch_bounds__(256) void k2_prep(const float* __restrict__ a_vec) {
    const int row  = blockIdx.x * 8 + (threadIdx.x >> 5);
    const int lane = threadIdx.x & 31;
    float h0 = g_h[row * FOUT + lane];
    float h1 = g_h[row * FOUT + 32 + lane];
    float s1 = h0 * a_vec[lane] + h1 * a_vec[32 + lane];
    float s2 = h0 * a_vec[64 + lane] + h1 * a_vec[96 + lane];
#pragma unroll
    for (int o = 16; o > 0; o >>= 1) {
        s1 += __shfl_xor_sync(0xffffffffu, s1, o);
        s2 += __shfl_xor_sync(0xffffffffu, s2, o);
    }
    if (lane == 0) {
        g_row[row] = make_float4(s1, expf(s1), expf(0.2f * s1), 0.f);
        g_col[row] = make_float4(s2, expf(s2), expf(0.2f * s2), 0.f);
    }
    g_hextT[lane * NN + row]        = __float2half_rn(h0);
    g_hextT[(lane + 32) * NN + row] = __float2half_rn(h1);
}

// ==================== K3: coalesced adj, wgen->smem, ldmatrix A+B, fp16 MMA ======
// grid (64 row-blocks, 4 j-splits), 256 threads = 8 warps, warp owns 16 M rows.
__global__ __launch_bounds__(256, 2) void k3_main(const int* __restrict__ adj) {
    __shared__ __half  w_sm[2][BM][PAD];     // 36.9 KB  A tile (fp16 weights)
    __shared__ __half  hT_sm[2][FOUT][PAD];  // 18.4 KB  B tile
    __shared__ float4  col_sm[4][BK];        // 4 KB     col factor ring
    __shared__ float4  row_sm[BM];           // 2 KB     row factors

    const int t    = threadIdx.x;
    const int warp = t >> 5, lane = t & 31;
    const int ib   = blockIdx.x * BM;
    const int j0   = blockIdx.y * JPER;

    // loader/wgen mapping: seg = t&15 (4 consecutive j), rows (t>>4)+16q
    const int seg  = t & 15;
    const int rloc = t >> 4;   // 0..15
    const int jc0  = j0 + seg * 4;

    // mma mapping
    const int g = lane >> 2, tq = lane & 3;
    const int mrow = warp * 16;

    const uint32_t w_base  = smem_u32(&w_sm[0][0][0]);
    const uint32_t hT_base = smem_u32(&hT_sm[0][0][0]);
    // A-frag ldmatrix lane offset: tile = lane>>3 (0..3)
    const int a_tile = lane >> 3, a_rin = lane & 7;
    const uint32_t a_lane_off =
        (uint32_t)((mrow + a_rin + (a_tile & 1) * 8) * (PAD * 2) + (a_tile >> 1) * 16);
    // B-frag ldmatrix lane offset (same as R5, verified)
    const uint32_t b_lane_off =
        (uint32_t)((((lane >> 4) & 1) * 8 + (lane & 7)) * (PAD * 2) +
                   ((lane >> 3) & 1) * 16);

    float acc[NF][4];
#pragma unroll
    for (int nf = 0; nf < NF; nf++)
#pragma unroll
        for (int q = 0; q < 4; q++) acc[nf][q] = 0.f;
    float dden[8];
#pragma unroll
    for (int q = 0; q < 8; q++) dden[q] = 0.f;

    auto stage_hT = [&](int buf, int ch) {
        const int jg = j0 + ch * BK;
#pragma unroll
        for (int m = 0; m < 2; m++) {
            int lin = t + m * 256;
            int n = lin >> 3, s2 = lin & 7;
            *(uint4*)&hT_sm[buf][n][s2 * 8] =
                *(const uint4*)&g_hextT[n * NN + jg + s2 * 8];
        }
    };
    auto stage_col = [&](int slot, int ch) {
        if (t < BK) col_sm[slot][t] = g_col[j0 + ch * BK + t];
    };
    auto ld_adj = [&](int ch, int4* R) {
        const int* p = adj + (size_t)(ib + rloc) * NN + jc0 + ch * BK;
#pragma unroll
        for (int q = 0; q < 8; q++)
            R[q] = *(const int4*)&p[(size_t)q * 16 * NN];
    };
    auto gen_w = [&](int buf, int slot, const int4* R) {
        const float4 c0 = col_sm[slot][seg * 4 + 0];
        const float4 c1 = col_sm[slot][seg * 4 + 1];
        const float4 c2 = col_sm[slot][seg * 4 + 2];
        const float4 c3 = col_sm[slot][seg * 4 + 3];
#pragma unroll
        for (int q = 0; q < 8; q++) {
            const float4 rv = row_sm[rloc + 16 * q];
            float w0 = wgen(rv.x, rv.y, rv.z, c0, R[q].x);
            float w1 = wgen(rv.x, rv.y, rv.z, c1, R[q].y);
            float w2 = wgen(rv.x, rv.y, rv.z, c2, R[q].z);
            float w3 = wgen(rv.x, rv.y, rv.z, c3, R[q].w);
            dden[q] += (w0 + w1) + (w2 + w3);
            uint2 p = make_uint2(packh2(w0, w1), packh2(w2, w3));
            *(uint2*)&w_sm[buf][rloc + 16 * q][seg * 4] = p;
        }
    };

    // ---- prologue ----
    {
        for (int m = t; m < BM; m += 256) row_sm[m] = g_row[ib + m];
        stage_col(0, 0);
        stage_col(1, 1);
        stage_hT(0, 0);
        int4 R[8];
        ld_adj(0, R);
        __syncthreads();
        gen_w(0, 0, R);
    }

    // ---- main loop ----
    for (int ch = 0; ch < CHUNKS; ch++) {
        const int buf = ch & 1;
        int4 R[8];
        if (ch + 1 < CHUNKS) ld_adj(ch + 1, R);

        __syncthreads();   // w[buf], hT[buf] ready; mma(buf^1) of ch-1 complete

        if (ch + 1 < CHUNKS) {
            stage_hT(buf ^ 1, ch + 1);
            if (ch + 2 < CHUNKS) stage_col((ch + 2) & 3, ch + 2);
        }

        const uint32_t wb = w_base + (uint32_t)buf * (BM * PAD * 2) + a_lane_off;
        const uint32_t hb = hT_base + (uint32_t)buf * (FOUT * PAD * 2) + b_lane_off;
#pragma unroll
        for (int k16 = 0; k16 < 4; k16++) {
            uint32_t a[4];
            ldsm_x4(a[0], a[1], a[2], a[3], wb + (uint32_t)(k16 * 32));
            const uint32_t kaddr = hb + (uint32_t)(k16 * 32);
#pragma unroll
            for (int nfp = 0; nfp < 4; nfp++) {
                uint32_t b00, b01, b10, b11;
                ldsm_x4(b00, b01, b10, b11,
                        kaddr + (uint32_t)(nfp * 16 * (PAD * 2)));
                uint32_t bl[2] = {b00, b01};
                mma16816(acc[nfp * 2], a, bl);
                uint32_t bh[2] = {b10, b11};
                mma16816(acc[nfp * 2 + 1], a, bh);
            }
        }

        if (ch + 1 < CHUNKS) gen_w(buf ^ 1, (ch + 1) & 3, R);
    }

    // ---- denominator: reduce 16 seg lanes (half-warp) per row ----
#pragma unroll
    for (int q = 0; q < 8; q++) {
        float v = dden[q];
        v += __shfl_xor_sync(0xffffffffu, v, 1);
        v += __shfl_xor_sync(0xffffffffu, v, 2);
        v += __shfl_xor_sync(0xffffffffu, v, 4);
        v += __shfl_xor_sync(0xffffffffu, v, 8);
        if (seg == 0)
            g_den[blockIdx.y * NN + ib + rloc + 16 * q] = v;
    }

    // ---- store numerator partials ----
    float* P = &g_partial[(size_t)blockIdx.y * (NN * FOUT)];
    const int ra = ib + mrow + g;
    const int rb = ra + 8;
#pragma unroll
    for (int nf = 0; nf < NF; nf++) {
        const int col = nf * 8 + tq * 2;
        *(float2*)&P[(size_t)ra * FOUT + col] = make_float2(acc[nf][0], acc[nf][1]);
        *(float2*)&P[(size_t)rb * FOUT + col] = make_float2(acc[nf][2], acc[nf][3]);
    }
}

// ==================== K4: reduce splits, softmax divide, ELU ====================
__global__ __launch_bounds__(256) void k4_finish(float* __restrict__ out) {
    const int gid = blockIdx.x * 256 + threadIdx.x;   // 524288 total
    const int i = gid >> 6, f = gid & 63;
    float num = 0.f, den = 0.f;
#pragma unroll
    for (int s = 0; s < SPLITS; s++) {
        num += g_partial[((size_t)s * NN + i) * FOUT + f];
        den += g_den[s * NN + i];
    }
    float v = num / den;
    out[gid] = (v > 0.f) ? v : expm1f(v);
}

// ==================== launcher ====================
extern "C" void kernel_launch(void* const* d_in, const int* in_sizes, int n_in,
                              void* d_out, int out_size) {
    const float* inp   = (const float*)d_in[0];   // [8192,512]
    const int*   adj   = (const int*)d_in[1];     // [8192,8192]
    const float* W     = (const float*)d_in[2];   // [512,64]
    const float* a_vec = (const float*)d_in[3];   // [128,1]
    float* out = (float*)d_out;

    k1_gemm<<<NN / 64, 256>>>(inp, W);
    k2_prep<<<NN / 8, 256>>>(a_vec);
    k3_main<<<dim3(NN / BM, SPLITS), 256>>>(adj);
    k4_finish<<<(NN * FOUT) / 256, 256>>>(out);
}

// round 7
// speedup vs baseline: 1.6548x; 1.0681x over previous
#include <cuda_runtime.h>
#include <cuda_fp16.h>
#include <cuda_bf16.h>
#include <cstdint>

// Problem constants
#define NN   8192
#define FIN  512
#define FOUT 64
#define NF   8                // 64 N cols / 8 per mma
#define SPLITS 4
#define JPER  (NN / SPLITS)   // 2048 j per split
#define BK    64
#define CHUNKS (JPER / BK)    // 32
#define BM    128             // rows per k3 block
#define PAD   72              // smem row stride in halves (144B, ldmatrix conflict-free)

// -------- scratch (static device globals; no allocations allowed) --------
__device__ float  g_h[NN * FOUT];                // 2 MB   fp32 h = inp@W
__device__ float4 g_row[NN];                     // (f1, exp(f1), exp(0.2 f1), 0)
__device__ float4 g_col[NN];                     // (f2, exp(f2), exp(0.2 f2), 0)
__device__ __half g_hextT[FOUT * NN];            // 1 MB  transposed h fp16
__device__ float  g_partial[SPLITS * NN * FOUT]; // 8.4 MB per-split numerators
__device__ float  g_den[SPLITS * NN];            // per-split denominators

// -------- packed f32x2 FMA (Blackwell) --------
#define FMA_F32X2(d, a, b, c) \
    asm("fma.rn.f32x2 %0, %1, %2, %3;" : "=l"(d) : "l"(a), "l"(b), "l"(c))

__device__ __forceinline__ void mma16816(float* c, const uint32_t* a, const uint32_t* b) {
    asm volatile(
        "mma.sync.aligned.m16n8k16.row.col.f32.f16.f16.f32 "
        "{%0,%1,%2,%3}, {%4,%5,%6,%7}, {%8,%9}, {%0,%1,%2,%3};"
        : "+f"(c[0]), "+f"(c[1]), "+f"(c[2]), "+f"(c[3])
        : "r"(a[0]), "r"(a[1]), "r"(a[2]), "r"(a[3]), "r"(b[0]), "r"(b[1]));
}

__device__ __forceinline__ void ldsm_x4(uint32_t& r0, uint32_t& r1, uint32_t& r2,
                                        uint32_t& r3, uint32_t addr) {
    asm volatile("ldmatrix.sync.aligned.m8n8.x4.shared.b16 {%0,%1,%2,%3}, [%4];"
                 : "=r"(r0), "=r"(r1), "=r"(r2), "=r"(r3) : "r"(addr));
}

__device__ __forceinline__ uint32_t smem_u32(const void* p) {
    uint32_t a;
    asm("{ .reg .u64 t; cvta.to.shared.u64 t, %1; cvt.u32.u64 %0, t; }"
        : "=r"(a) : "l"(p));
    return a;
}

__device__ __forceinline__ float wgen(float rx, float ry, float rz,
                                      const float4 c, int m) {
    float x = rx + c.x;
    float w = (x > 0.f) ? ry * c.y : rz * c.z;
    return m ? w : 0.f;
}

__device__ __forceinline__ uint32_t packh2(float lo, float hi) {
    __half2 h = __floats2half2_rn(lo, hi);
    return *(uint32_t*)&h;
}

// ==================== K1: h = inp @ W  (fp32, f32x2 packed) ====================
__global__ __launch_bounds__(256) void k1_gemm(const float* __restrict__ inp,
                                               const float* __restrict__ W) {
    __shared__ float inp_s[64][68];
    __shared__ float w_sT[64][68];
    const int t  = threadIdx.x;
    const int i0 = blockIdx.x * 64;
    const int tx = t & 15;
    const int ty = t >> 4;

    unsigned long long acc2[4][4];
#pragma unroll
    for (int q = 0; q < 4; q++)
#pragma unroll
        for (int c = 0; c < 4; c++) acc2[q][c] = 0ULL;

    for (int kc = 0; kc < FIN; kc += 64) {
#pragma unroll
        for (int m = 0; m < 4; m++) {
            int lin = t + 256 * m;
            int row = lin >> 4, seg = lin & 15;
            float4 v  = *(const float4*)&inp[(i0 + row) * FIN + kc + seg * 4];
            *(float4*)&inp_s[row][seg * 4] = v;
            float4 wv = *(const float4*)&W[(kc + row) * FOUT + seg * 4];
            w_sT[seg * 4 + 0][row] = wv.x;
            w_sT[seg * 4 + 1][row] = wv.y;
            w_sT[seg * 4 + 2][row] = wv.z;
            w_sT[seg * 4 + 3][row] = wv.w;
        }
        __syncthreads();
#pragma unroll 4
        for (int kk = 0; kk < 64; kk += 2) {
            unsigned long long a2[4], b2[4];
#pragma unroll
            for (int q = 0; q < 4; q++)
                a2[q] = *(const unsigned long long*)&inp_s[ty * 4 + q][kk];
#pragma unroll
            for (int c = 0; c < 4; c++)
                b2[c] = *(const unsigned long long*)&w_sT[tx * 4 + c][kk];
#pragma unroll
            for (int q = 0; q < 4; q++)
#pragma unroll
                for (int c = 0; c < 4; c++)
                    FMA_F32X2(acc2[q][c], a2[q], b2[c], acc2[q][c]);
        }
        __syncthreads();
    }
#pragma unroll
    for (int q = 0; q < 4; q++)
#pragma unroll
        for (int c = 0; c < 4; c++) {
            float lo, hi;
            asm("mov.b64 {%0,%1}, %2;" : "=f"(lo), "=f"(hi) : "l"(acc2[q][c]));
            g_h[(i0 + ty * 4 + q) * FOUT + tx * 4 + c] = lo + hi;
        }
}

// ==================== K2: per-node f1/f2, exp factors, hT fp16 ==================
__global__ __launch_bounds__(256) void k2_prep(const float* __restrict__ a_vec) {
    const int row  = blockIdx.x * 8 + (threadIdx.x >> 5);
    const int lane = threadIdx.x & 31;
    float h0 = g_h[row * FOUT + lane];
    float h1 = g_h[row * FOUT + 32 + lane];
    float s1 = h0 * a_vec[lane] + h1 * a_vec[32 + lane];
    float s2 = h0 * a_vec[64 + lane] + h1 * a_vec[96 + lane];
#pragma unroll
    for (int o = 16; o > 0; o >>= 1) {
        s1 += __shfl_xor_sync(0xffffffffu, s1, o);
        s2 += __shfl_xor_sync(0xffffffffu, s2, o);
    }
    if (lane == 0) {
        g_row[row] = make_float4(s1, expf(s1), expf(0.2f * s1), 0.f);
        g_col[row] = make_float4(s2, expf(s2), expf(0.2f * s2), 0.f);
    }
    g_hextT[lane * NN + row]        = __float2half_rn(h0);
    g_hextT[(lane + 32) * NN + row] = __float2half_rn(h1);
}

// ==================== K3: staggered wgen/MMA phases across warps =================
// grid (64 row-blocks, 4 j-splits), 256 threads = 8 warps, warp owns 16 M rows.
// Odd warps: gen_w(ch+1) then mma(ch). Even warps: mma(ch) then gen_w(ch+1).
// -> tensor pipe and fma pipe overlap across warps instead of running serially.
__global__ __launch_bounds__(256, 2) void k3_main(const int* __restrict__ adj) {
    __shared__ __half  w_sm[2][BM][PAD];     // 36.9 KB  A tile (fp16 weights)
    __shared__ __half  hT_sm[2][FOUT][PAD];  // 18.4 KB  B tile
    __shared__ float4  col_sm[4][BK];        // 4 KB     col factor ring
    __shared__ float4  row_sm[BM];           // 2 KB     row factors

    const int t    = threadIdx.x;
    const int warp = t >> 5, lane = t & 31;
    const int ib   = blockIdx.x * BM;
    const int j0   = blockIdx.y * JPER;

    // loader/wgen mapping: seg = t&15 (4 consecutive j), rows (t>>4)+16q
    const int seg  = t & 15;
    const int rloc = t >> 4;   // 0..15
    const int jc0  = j0 + seg * 4;

    // mma mapping
    const int g = lane >> 2, tq = lane & 3;
    const int mrow = warp * 16;

    const uint32_t w_base  = smem_u32(&w_sm[0][0][0]);
    const uint32_t hT_base = smem_u32(&hT_sm[0][0][0]);
    const int a_tile = lane >> 3, a_rin = lane & 7;
    const uint32_t a_lane_off =
        (uint32_t)((mrow + a_rin + (a_tile & 1) * 8) * (PAD * 2) + (a_tile >> 1) * 16);
    const uint32_t b_lane_off =
        (uint32_t)((((lane >> 4) & 1) * 8 + (lane & 7)) * (PAD * 2) +
                   ((lane >> 3) & 1) * 16);

    float acc[NF][4];
#pragma unroll
    for (int nf = 0; nf < NF; nf++)
#pragma unroll
        for (int q = 0; q < 4; q++) acc[nf][q] = 0.f;
    float dden[8];
#pragma unroll
    for (int q = 0; q < 8; q++) dden[q] = 0.f;

    auto stage_hT = [&](int buf, int ch) {
        const int jg = j0 + ch * BK;
#pragma unroll
        for (int m = 0; m < 2; m++) {
            int lin = t + m * 256;
            int n = lin >> 3, s2 = lin & 7;
            *(uint4*)&hT_sm[buf][n][s2 * 8] =
                *(const uint4*)&g_hextT[n * NN + jg + s2 * 8];
        }
    };
    auto stage_col = [&](int slot, int ch) {
        if (t < BK) col_sm[slot][t] = g_col[j0 + ch * BK + t];
    };
    auto ld_adj = [&](int ch, int4* R) {
        const int* p = adj + (size_t)(ib + rloc) * NN + jc0 + ch * BK;
#pragma unroll
        for (int q = 0; q < 8; q++)
            R[q] = *(const int4*)&p[(size_t)q * 16 * NN];
    };
    auto gen_w = [&](int buf, int slot, const int4* R) {
        const float4 c0 = col_sm[slot][seg * 4 + 0];
        const float4 c1 = col_sm[slot][seg * 4 + 1];
        const float4 c2 = col_sm[slot][seg * 4 + 2];
        const float4 c3 = col_sm[slot][seg * 4 + 3];
#pragma unroll
        for (int q = 0; q < 8; q++) {
            const float4 rv = row_sm[rloc + 16 * q];
            float w0 = wgen(rv.x, rv.y, rv.z, c0, R[q].x);
            float w1 = wgen(rv.x, rv.y, rv.z, c1, R[q].y);
            float w2 = wgen(rv.x, rv.y, rv.z, c2, R[q].z);
            float w3 = wgen(rv.x, rv.y, rv.z, c3, R[q].w);
            dden[q] += (w0 + w1) + (w2 + w3);
            uint2 p = make_uint2(packh2(w0, w1), packh2(w2, w3));
            *(uint2*)&w_sm[buf][rloc + 16 * q][seg * 4] = p;
        }
    };
    auto mma_chunk = [&](int buf) {
        const uint32_t wb = w_base + (uint32_t)buf * (BM * PAD * 2) + a_lane_off;
        const uint32_t hb = hT_base + (uint32_t)buf * (FOUT * PAD * 2) + b_lane_off;
#pragma unroll
        for (int k16 = 0; k16 < 4; k16++) {
            uint32_t a[4];
            ldsm_x4(a[0], a[1], a[2], a[3], wb + (uint32_t)(k16 * 32));
            const uint32_t kaddr = hb + (uint32_t)(k16 * 32);
#pragma unroll
            for (int nfp = 0; nfp < 4; nfp++) {
                uint32_t b00, b01, b10, b11;
                ldsm_x4(b00, b01, b10, b11,
                        kaddr + (uint32_t)(nfp * 16 * (PAD * 2)));
                uint32_t bl[2] = {b00, b01};
                mma16816(acc[nfp * 2], a, bl);
                uint32_t bh[2] = {b10, b11};
                mma16816(acc[nfp * 2 + 1], a, bh);
            }
        }
    };

    // ---- prologue ----
    {
        for (int m = t; m < BM; m += 256) row_sm[m] = g_row[ib + m];
        stage_col(0, 0);
        stage_col(1, 1);
        stage_hT(0, 0);
        int4 R[8];
        ld_adj(0, R);
        __syncthreads();
        gen_w(0, 0, R);
    }

    // ---- main loop: staggered phases ----
    for (int ch = 0; ch < CHUNKS; ch++) {
        const int buf = ch & 1;
        int4 R[8];
        if (ch + 1 < CHUNKS) ld_adj(ch + 1, R);

        __syncthreads();   // w[buf], hT[buf] ready; mma(buf^1) of ch-1 complete

        if (ch + 1 < CHUNKS) {
            stage_hT(buf ^ 1, ch + 1);
            if (ch + 2 < CHUNKS) stage_col((ch + 2) & 3, ch + 2);
        }

        if (warp & 1) {
            if (ch + 1 < CHUNKS) gen_w(buf ^ 1, (ch + 1) & 3, R);
            mma_chunk(buf);
        } else {
            mma_chunk(buf);
            if (ch + 1 < CHUNKS) gen_w(buf ^ 1, (ch + 1) & 3, R);
        }
    }

    // ---- denominator: reduce 16 seg lanes (half-warp) per row ----
#pragma unroll
    for (int q = 0; q < 8; q++) {
        float v = dden[q];
        v += __shfl_xor_sync(0xffffffffu, v, 1);
        v += __shfl_xor_sync(0xffffffffu, v, 2);
        v += __shfl_xor_sync(0xffffffffu, v, 4);
        v += __shfl_xor_sync(0xffffffffu, v, 8);
        if (seg == 0)
            g_den[blockIdx.y * NN + ib + rloc + 16 * q] = v;
    }

    // ---- store numerator partials ----
    float* P = &g_partial[(size_t)blockIdx.y * (NN * FOUT)];
    const int ra = ib + mrow + g;
    const int rb = ra + 8;
#pragma unroll
    for (int nf = 0; nf < NF; nf++) {
        const int col = nf * 8 + tq * 2;
        *(float2*)&P[(size_t)ra * FOUT + col] = make_float2(acc[nf][0], acc[nf][1]);
        *(float2*)&P[(size_t)rb * FOUT + col] = make_float2(acc[nf][2], acc[nf][3]);
    }
}

// ==================== K4: reduce splits, softmax divide, ELU ====================
__global__ __launch_bounds__(256) void k4_finish(float* __restrict__ out) {
    const int gid = blockIdx.x * 256 + threadIdx.x;   // 524288 total
    const int i = gid >> 6, f = gid & 63;
    float num = 0.f, den = 0.f;
#pragma unroll
    for (int s = 0; s < SPLITS; s++) {
        num += g_partial[((size_t)s * NN + i) * FOUT + f];
        den += g_den[s * NN + i];
    }
    float v = num / den;
    out[gid] = (v > 0.f) ? v : expm1f(v);
}

// ==================== launcher ====================
extern "C" void kernel_launch(void* const* d_in, const int* in_sizes, int n_in,
                              void* d_out, int out_size) {
    const float* inp   = (const float*)d_in[0];   // [8192,512]
    const int*   adj   = (const int*)d_in[1];     // [8192,8192]
    const float* W     = (const float*)d_in[2];   // [512,64]
    const float* a_vec = (const float*)d_in[3];   // [128,1]
    float* out = (float*)d_out;

    k1_gemm<<<NN / 64, 256>>>(inp, W);
    k2_prep<<<NN / 8, 256>>>(a_vec);
    k3_main<<<dim3(NN / BM, SPLITS), 256>>>(adj);
    k4_finish<<<(NN * FOUT) / 256, 256>>>(out);
}

// round 8
// speedup vs baseline: 1.6852x; 1.0183x over previous
#include <cuda_runtime.h>
#include <cuda_fp16.h>
#include <cuda_bf16.h>
#include <cstdint>

// Problem constants
#define NN   8192
#define FIN  512
#define FOUT 64
#define NF   8                // 64 N cols / 8 per mma
#define SPLITS 4
#define JPER  (NN / SPLITS)   // 2048 j per split
#define BK    64
#define CHUNKS (JPER / BK)    // 32
#define BM    128             // rows per k3 block
#define PAD   72              // smem row stride in halves (144B, ldmatrix conflict-free)

// -------- scratch (static device globals; no allocations allowed) --------
__device__ float  g_h[NN * FOUT];                // 2 MB   fp32 h = inp@W
__device__ float2 g_row[NN];                     // (exp(f1), exp(0.2 f1))
__device__ float2 g_col[NN];                     // (exp(f2), exp(0.2 f2))
__device__ __half g_hextT[FOUT * NN];            // 1 MB  transposed h fp16
__device__ float  g_partial[SPLITS * NN * FOUT]; // 8.4 MB per-split numerators
__device__ float  g_den[SPLITS * NN];            // per-split denominators

// -------- packed f32x2 FMA (Blackwell) --------
#define FMA_F32X2(d, a, b, c) \
    asm("fma.rn.f32x2 %0, %1, %2, %3;" : "=l"(d) : "l"(a), "l"(b), "l"(c))

// fp16-accumulator mma: D,C are 2 regs (4 halves)
__device__ __forceinline__ void mma16816h(uint32_t* c, const uint32_t* a,
                                          const uint32_t* b) {
    asm volatile(
        "mma.sync.aligned.m16n8k16.row.col.f16.f16.f16.f16 "
        "{%0,%1}, {%2,%3,%4,%5}, {%6,%7}, {%0,%1};"
        : "+r"(c[0]), "+r"(c[1])
        : "r"(a[0]), "r"(a[1]), "r"(a[2]), "r"(a[3]), "r"(b[0]), "r"(b[1]));
}

__device__ __forceinline__ void ldsm_x4(uint32_t& r0, uint32_t& r1, uint32_t& r2,
                                        uint32_t& r3, uint32_t addr) {
    asm volatile("ldmatrix.sync.aligned.m8n8.x4.shared.b16 {%0,%1,%2,%3}, [%4];"
                 : "=r"(r0), "=r"(r1), "=r"(r2), "=r"(r3) : "r"(addr));
}

__device__ __forceinline__ uint32_t smem_u32(const void* p) {
    uint32_t a;
    asm("{ .reg .u64 t; cvta.to.shared.u64 t, %1; cvt.u32.u64 %0, t; }"
        : "=r"(a) : "l"(p));
    return a;
}

// exp(lrelu(f1+f2)) = max(EA*EC, EB*ED)  (exp is monotone) ; mask via fp mul
__device__ __forceinline__ float wgen(float2 rv, float2 c, int m) {
    float w = fmaxf(rv.x * c.x, rv.y * c.y);
    return w * __int_as_float(m * 0x3F800000);
}

__device__ __forceinline__ uint32_t packh2(float lo, float hi) {
    __half2 h = __floats2half2_rn(lo, hi);
    return *(uint32_t*)&h;
}

// ==================== K1: h = inp @ W  (fp32, f32x2 packed) ====================
__global__ __launch_bounds__(256) void k1_gemm(const float* __restrict__ inp,
                                               const float* __restrict__ W) {
    __shared__ float inp_s[64][68];
    __shared__ float w_sT[64][68];
    const int t  = threadIdx.x;
    const int i0 = blockIdx.x * 64;
    const int tx = t & 15;
    const int ty = t >> 4;

    unsigned long long acc2[4][4];
#pragma unroll
    for (int q = 0; q < 4; q++)
#pragma unroll
        for (int c = 0; c < 4; c++) acc2[q][c] = 0ULL;

    for (int kc = 0; kc < FIN; kc += 64) {
#pragma unroll
        for (int m = 0; m < 4; m++) {
            int lin = t + 256 * m;
            int row = lin >> 4, seg = lin & 15;
            float4 v  = *(const float4*)&inp[(i0 + row) * FIN + kc + seg * 4];
            *(float4*)&inp_s[row][seg * 4] = v;
            float4 wv = *(const float4*)&W[(kc + row) * FOUT + seg * 4];
            w_sT[seg * 4 + 0][row] = wv.x;
            w_sT[seg * 4 + 1][row] = wv.y;
            w_sT[seg * 4 + 2][row] = wv.z;
            w_sT[seg * 4 + 3][row] = wv.w;
        }
        __syncthreads();
#pragma unroll 4
        for (int kk = 0; kk < 64; kk += 2) {
            unsigned long long a2[4], b2[4];
#pragma unroll
            for (int q = 0; q < 4; q++)
                a2[q] = *(const unsigned long long*)&inp_s[ty * 4 + q][kk];
#pragma unroll
            for (int c = 0; c < 4; c++)
                b2[c] = *(const unsigned long long*)&w_sT[tx * 4 + c][kk];
#pragma unroll
            for (int q = 0; q < 4; q++)
#pragma unroll
                for (int c = 0; c < 4; c++)
                    FMA_F32X2(acc2[q][c], a2[q], b2[c], acc2[q][c]);
        }
        __syncthreads();
    }
#pragma unroll
    for (int q = 0; q < 4; q++)
#pragma unroll
        for (int c = 0; c < 4; c++) {
            float lo, hi;
            asm("mov.b64 {%0,%1}, %2;" : "=f"(lo), "=f"(hi) : "l"(acc2[q][c]));
            g_h[(i0 + ty * 4 + q) * FOUT + tx * 4 + c] = lo + hi;
        }
}

// ==================== K2: per-node exp factors, hT fp16 =========================
__global__ __launch_bounds__(256) void k2_prep(const float* __restrict__ a_vec) {
    const int row  = blockIdx.x * 8 + (threadIdx.x >> 5);
    const int lane = threadIdx.x & 31;
    float h0 = g_h[row * FOUT + lane];
    float h1 = g_h[row * FOUT + 32 + lane];
    float s1 = h0 * a_vec[lane] + h1 * a_vec[32 + lane];
    float s2 = h0 * a_vec[64 + lane] + h1 * a_vec[96 + lane];
#pragma unroll
    for (int o = 16; o > 0; o >>= 1) {
        s1 += __shfl_xor_sync(0xffffffffu, s1, o);
        s2 += __shfl_xor_sync(0xffffffffu, s2, o);
    }
    if (lane == 0) {
        g_row[row] = make_float2(expf(s1), expf(0.2f * s1));
        g_col[row] = make_float2(expf(s2), expf(0.2f * s2));
    }
    g_hextT[lane * NN + row]        = __float2half_rn(h0);
    g_hextT[(lane + 32) * NN + row] = __float2half_rn(h1);
}

// ==================== K3: max-trick wgen + fp16-acc MMA, staggered ==============
__global__ __launch_bounds__(256, 2) void k3_main(const int* __restrict__ adj) {
    __shared__ __half  w_sm[2][BM][PAD];     // 36.9 KB  A tile (fp16 weights)
    __shared__ __half  hT_sm[2][FOUT][PAD];  // 18.4 KB  B tile
    __shared__ float2  col_sm[4][BK];        // 2 KB     col factor ring
    __shared__ float2  row_sm[BM];           // 1 KB     row factors

    const int t    = threadIdx.x;
    const int warp = t >> 5, lane = t & 31;
    const int ib   = blockIdx.x * BM;
    const int j0   = blockIdx.y * JPER;

    const int seg  = t & 15;
    const int rloc = t >> 4;   // 0..15
    const int jc0  = j0 + seg * 4;

    const int g = lane >> 2, tq = lane & 3;
    const int mrow = warp * 16;

    const uint32_t w_base  = smem_u32(&w_sm[0][0][0]);
    const uint32_t hT_base = smem_u32(&hT_sm[0][0][0]);
    const int a_tile = lane >> 3, a_rin = lane & 7;
    const uint32_t a_lane_off =
        (uint32_t)((mrow + a_rin + (a_tile & 1) * 8) * (PAD * 2) + (a_tile >> 1) * 16);
    const uint32_t b_lane_off =
        (uint32_t)((((lane >> 4) & 1) * 8 + (lane & 7)) * (PAD * 2) +
                   ((lane >> 3) & 1) * 16);

    float accf[NF][4];
    uint32_t acch[NF][2];
#pragma unroll
    for (int nf = 0; nf < NF; nf++) {
#pragma unroll
        for (int q = 0; q < 4; q++) accf[nf][q] = 0.f;
        acch[nf][0] = 0u; acch[nf][1] = 0u;
    }
    float dden[8];
#pragma unroll
    for (int q = 0; q < 8; q++) dden[q] = 0.f;

    auto stage_hT = [&](int buf, int ch) {
        const int jg = j0 + ch * BK;
#pragma unroll
        for (int m = 0; m < 2; m++) {
            int lin = t + m * 256;
            int n = lin >> 3, s2 = lin & 7;
            *(uint4*)&hT_sm[buf][n][s2 * 8] =
                *(const uint4*)&g_hextT[n * NN + jg + s2 * 8];
        }
    };
    auto stage_col = [&](int slot, int ch) {
        if (t < BK) col_sm[slot][t] = g_col[j0 + ch * BK + t];
    };
    auto ld_adj = [&](int ch, int4* R) {
        const int* p = adj + (size_t)(ib + rloc) * NN + jc0 + ch * BK;
#pragma unroll
        for (int q = 0; q < 8; q++)
            R[q] = *(const int4*)&p[(size_t)q * 16 * NN];
    };
    auto gen_w = [&](int buf, int slot, const int4* R) {
        const float2 c0 = col_sm[slot][seg * 4 + 0];
        const float2 c1 = col_sm[slot][seg * 4 + 1];
        const float2 c2 = col_sm[slot][seg * 4 + 2];
        const float2 c3 = col_sm[slot][seg * 4 + 3];
#pragma unroll
        for (int q = 0; q < 8; q++) {
            const float2 rv = row_sm[rloc + 16 * q];
            float w0 = wgen(rv, c0, R[q].x);
            float w1 = wgen(rv, c1, R[q].y);
            float w2 = wgen(rv, c2, R[q].z);
            float w3 = wgen(rv, c3, R[q].w);
            dden[q] += (w0 + w1) + (w2 + w3);
            uint2 p = make_uint2(packh2(w0, w1), packh2(w2, w3));
            *(uint2*)&w_sm[buf][rloc + 16 * q][seg * 4] = p;
        }
    };
    auto mma_chunk = [&](int buf) {
        const uint32_t wb = w_base + (uint32_t)buf * (BM * PAD * 2) + a_lane_off;
        const uint32_t hb = hT_base + (uint32_t)buf * (FOUT * PAD * 2) + b_lane_off;
#pragma unroll
        for (int k16 = 0; k16 < 4; k16++) {
            uint32_t a[4];
            ldsm_x4(a[0], a[1], a[2], a[3], wb + (uint32_t)(k16 * 32));
            const uint32_t kaddr = hb + (uint32_t)(k16 * 32);
#pragma unroll
            for (int nfp = 0; nfp < 4; nfp++) {
                uint32_t b00, b01, b10, b11;
                ldsm_x4(b00, b01, b10, b11,
                        kaddr + (uint32_t)(nfp * 16 * (PAD * 2)));
                uint32_t bl[2] = {b00, b01};
                mma16816h(acch[nfp * 2], a, bl);
                uint32_t bh[2] = {b10, b11};
                mma16816h(acch[nfp * 2 + 1], a, bh);
            }
        }
    };

    // ---- prologue ----
    {
        for (int m = t; m < BM; m += 256) row_sm[m] = g_row[ib + m];
        stage_col(0, 0);
        stage_col(1, 1);
        stage_hT(0, 0);
        int4 R[8];
        ld_adj(0, R);
        __syncthreads();
        gen_w(0, 0, R);
    }

    // ---- main loop: staggered phases, fp16 acc flushed every 2 chunks ----
    for (int ch = 0; ch < CHUNKS; ch++) {
        const int buf = ch & 1;
        int4 R[8];
        if (ch + 1 < CHUNKS) ld_adj(ch + 1, R);

        __syncthreads();   // w[buf], hT[buf] ready; mma of ch-1 complete

        if (ch + 1 < CHUNKS) {
            stage_hT(buf ^ 1, ch + 1);
            if (ch + 2 < CHUNKS) stage_col((ch + 2) & 3, ch + 2);
        }

        if (warp & 1) {
            if (ch + 1 < CHUNKS) gen_w(buf ^ 1, (ch + 1) & 3, R);
            mma_chunk(buf);
        } else {
            mma_chunk(buf);
            if (ch + 1 < CHUNKS) gen_w(buf ^ 1, (ch + 1) & 3, R);
        }

        if (ch & 1) {   // flush fp16 partials to fp32 every 2 chunks
#pragma unroll
            for (int nf = 0; nf < NF; nf++) {
                float2 lo = __half22float2(*(__half2*)&acch[nf][0]);
                float2 hi = __half22float2(*(__half2*)&acch[nf][1]);
                accf[nf][0] += lo.x; accf[nf][1] += lo.y;
                accf[nf][2] += hi.x; accf[nf][3] += hi.y;
                acch[nf][0] = 0u; acch[nf][1] = 0u;
            }
        }
    }

    // ---- denominator: reduce 16 seg lanes (half-warp) per row ----
#pragma unroll
    for (int q = 0; q < 8; q++) {
        float v = dden[q];
        v += __shfl_xor_sync(0xffffffffu, v, 1);
        v += __shfl_xor_sync(0xffffffffu, v, 2);
        v += __shfl_xor_sync(0xffffffffu, v, 4);
        v += __shfl_xor_sync(0xffffffffu, v, 8);
        if (seg == 0)
            g_den[blockIdx.y * NN + ib + rloc + 16 * q] = v;
    }

    // ---- store numerator partials ----
    float* P = &g_partial[(size_t)blockIdx.y * (NN * FOUT)];
    const int ra = ib + mrow + g;
    const int rb = ra + 8;
#pragma unroll
    for (int nf = 0; nf < NF; nf++) {
        const int col = nf * 8 + tq * 2;
        *(float2*)&P[(size_t)ra * FOUT + col] = make_float2(accf[nf][0], accf[nf][1]);
        *(float2*)&P[(size_t)rb * FOUT + col] = make_float2(accf[nf][2], accf[nf][3]);
    }
}

// ==================== K4: reduce splits, softmax divide, ELU ====================
__global__ __launch_bounds__(256) void k4_finish(float* __restrict__ out) {
    const int gid = blockIdx.x * 256 + threadIdx.x;   // 524288 total
    const int i = gid >> 6, f = gid & 63;
    float num = 0.f, den = 0.f;
#pragma unroll
    for (int s = 0; s < SPLITS; s++) {
        num += g_partial[((size_t)s * NN + i) * FOUT + f];
        den += g_den[s * NN + i];
    }
    float v = num / den;
    out[gid] = (v > 0.f) ? v : expm1f(v);
}

// ==================== launcher ====================
extern "C" void kernel_launch(void* const* d_in, const int* in_sizes, int n_in,
                              void* d_out, int out_size) {
    const float* inp   = (const float*)d_in[0];   // [8192,512]
    const int*   adj   = (const int*)d_in[1];     // [8192,8192]
    const float* W     = (const float*)d_in[2];   // [512,64]
    const float* a_vec = (const float*)d_in[3];   // [128,1]
    float* out = (float*)d_out;

    k1_gemm<<<NN / 64, 256>>>(inp, W);
    k2_prep<<<NN / 8, 256>>>(a_vec);
    k3_main<<<dim3(NN / BM, SPLITS), 256>>>(adj);
    k4_finish<<<(NN * FOUT) / 256, 256>>>(out);
}